// round 2
// baseline (speedup 1.0000x reference)
#include <cuda_runtime.h>
#include <cuda_fp16.h>
#include <math.h>

#define N_NODES 50000
#define N_EDGES 1600000
// IN_DIM = 128, HEADS*HIDDEN = 128, OUT_DIM = 64

// ---------------- static device scratch ----------------
__device__ int    g_deg[N_NODES];
__device__ int    g_rs[N_NODES + 1];     // CSR row_start by dst
__device__ int    g_cur[N_NODES];        // fill cursors
__device__ int    g_col[N_EDGES];        // src indices grouped by dst
__device__ __half g_feat1h[N_NODES * 128];  // fp16 gather table, layer 1
__device__ float  g_h1[N_NODES * 128];      // fp32 input to gemm2
__device__ __half g_feat2h[N_NODES * 64];   // fp16 gather table, layer 2

// ---------------- CSR build ----------------
__global__ void k_reset() {
    int i = blockIdx.x * blockDim.x + threadIdx.x;
    if (i < N_NODES) g_deg[i] = 0;
}

__global__ void k_hist(const int* __restrict__ dst) {
    int i = blockIdx.x * blockDim.x + threadIdx.x;
    if (i < N_EDGES) atomicAdd(&g_deg[dst[i]], 1);
}

// single-block exclusive scan over 50000 degrees
__global__ void k_scan() {
    __shared__ int sums[1024];
    const int PER = (N_NODES + 1023) / 1024;  // 49
    int t = threadIdx.x;
    int beg = t * PER;
    int end = min(beg + PER, N_NODES);
    int s = 0;
    for (int i = beg; i < end; i++) s += g_deg[i];
    sums[t] = s;
    __syncthreads();
    for (int off = 1; off < 1024; off <<= 1) {
        int v = (t >= off) ? sums[t - off] : 0;
        __syncthreads();
        sums[t] += v;
        __syncthreads();
    }
    int run = (t == 0) ? 0 : sums[t - 1];
    for (int i = beg; i < end; i++) {
        g_rs[i]  = run;
        g_cur[i] = run;
        run += g_deg[i];
    }
    if (t == 1023) g_rs[N_NODES] = run;
}

__global__ void k_fill(const int* __restrict__ src, const int* __restrict__ dst) {
    int i = blockIdx.x * blockDim.x + threadIdx.x;
    if (i < N_EDGES) {
        int d = dst[i];
        int pos = atomicAdd(&g_cur[d], 1);
        g_col[pos] = src[i];
    }
}

// ---------------- GEMM: Yh[N, MOUT](fp16) = X[N, 128] @ W[128, MOUT] ----------------
// 128-row x MOUT-col tile per block, 256 threads, 8 x (MOUT/16) register blocking.
// Xs row-major with +1 pad (conflict-free scalar access), Ws k-major.
template <int MOUT>
__global__ __launch_bounds__(256) void k_gemm(const float* __restrict__ X,
                                              const float* __restrict__ W,
                                              __half* __restrict__ Yh,
                                              float* __restrict__ Yf) {
    constexpr int CPT = MOUT / 16;          // cols per thread: 8 or 4
    __shared__ float Xs[128][33];           // 16.9 KB
    __shared__ float Ws[32][MOUT];          // 16 KB (MOUT=128) / 8 KB

    const int tid = threadIdx.x;
    const int tx = tid & 15;                // 16 col groups
    const int ty = tid >> 4;                // 16 row groups of 8
    const int row0 = blockIdx.x * 128;

    float acc[8][CPT];
#pragma unroll
    for (int i = 0; i < 8; i++)
#pragma unroll
        for (int j = 0; j < CPT; j++) acc[i][j] = 0.f;

#pragma unroll
    for (int kt = 0; kt < 4; kt++) {
        // load Xs: 128 rows x 32 k, coalesced float4, scalar stores (conflict-free)
#pragma unroll
        for (int it = 0; it < 4; it++) {
            int idx = tid + it * 256;       // 0..1023
            int r = idx >> 3, kq = idx & 7;
            float4 v = make_float4(0.f, 0.f, 0.f, 0.f);
            int gr = row0 + r;
            if (gr < N_NODES)
                v = *reinterpret_cast<const float4*>(X + gr * 128 + kt * 32 + kq * 4);
            Xs[r][kq * 4 + 0] = v.x;
            Xs[r][kq * 4 + 1] = v.y;
            Xs[r][kq * 4 + 2] = v.z;
            Xs[r][kq * 4 + 3] = v.w;
        }
        // load Ws: 32 k x MOUT cols
        for (int idx = tid; idx < 32 * MOUT / 4; idx += 256) {
            int k = idx / (MOUT / 4), c4 = idx % (MOUT / 4);
            *reinterpret_cast<float4*>(&Ws[k][c4 * 4]) =
                *reinterpret_cast<const float4*>(W + (kt * 32 + k) * MOUT + c4 * 4);
        }
        __syncthreads();

#pragma unroll
        for (int kk = 0; kk < 32; kk++) {
            float b[CPT];
#pragma unroll
            for (int j4 = 0; j4 < CPT; j4 += 4) {
                float4 w = *reinterpret_cast<const float4*>(&Ws[kk][tx * CPT + j4]);
                b[j4 + 0] = w.x; b[j4 + 1] = w.y; b[j4 + 2] = w.z; b[j4 + 3] = w.w;
            }
            float a[8];
#pragma unroll
            for (int i = 0; i < 8; i++) a[i] = Xs[ty * 8 + i][kk];
#pragma unroll
            for (int i = 0; i < 8; i++)
#pragma unroll
                for (int j = 0; j < CPT; j++) acc[i][j] += a[i] * b[j];
        }
        __syncthreads();
    }

    // epilogue: write fp16 table (and optional fp32 copy)
#pragma unroll
    for (int i = 0; i < 8; i++) {
        int gr = row0 + ty * 8 + i;
        if (gr >= N_NODES) continue;
#pragma unroll
        for (int j = 0; j < CPT; j += 2) {
            __half2 hv = __float22half2_rn(make_float2(acc[i][j], acc[i][j + 1]));
            *reinterpret_cast<__half2*>(Yh + gr * MOUT + tx * CPT + j) = hv;
        }
        if (Yf) {
#pragma unroll
            for (int j = 0; j < CPT; j += 4) {
                float4 v = make_float4(acc[i][j], acc[i][j + 1], acc[i][j + 2], acc[i][j + 3]);
                *reinterpret_cast<float4*>(Yf + gr * MOUT + tx * CPT + j) = v;
            }
        }
    }
}

// ---------------- fused GAT layer 1 (fp16 gathers, fp32 math) ----------------
__device__ __forceinline__ float eluf(float x) {
    return x > 0.f ? x : expm1f(x);
}

__global__ __launch_bounds__(256) void k_gat1() {
    int w = (blockIdx.x * blockDim.x + threadIdx.x) >> 5;
    if (w >= N_NODES) return;
    int lane = threadIdx.x & 31;

    const __half* fp = g_feat1h;
    uint2 ud = *reinterpret_cast<const uint2*>(fp + w * 128 + lane * 4);
    float2 d01 = __half22float2(*reinterpret_cast<__half2*>(&ud.x));
    float2 d23 = __half22float2(*reinterpret_cast<__half2*>(&ud.y));

    float a0 = 0.f, a1 = 0.f, a2 = 0.f, a3 = 0.f, den = 0.f;

    int i = g_rs[w], end = g_rs[w + 1];
    for (; i + 1 < end; i += 2) {
        int s0 = g_col[i], s1 = g_col[i + 1];
        uint2 u0 = *reinterpret_cast<const uint2*>(fp + s0 * 128 + lane * 4);
        uint2 u1 = *reinterpret_cast<const uint2*>(fp + s1 * 128 + lane * 4);
        float2 f001 = __half22float2(*reinterpret_cast<__half2*>(&u0.x));
        float2 f023 = __half22float2(*reinterpret_cast<__half2*>(&u0.y));
        float2 f101 = __half22float2(*reinterpret_cast<__half2*>(&u1.x));
        float2 f123 = __half22float2(*reinterpret_cast<__half2*>(&u1.y));
        float p0 = f001.x * d01.x + f001.y * d01.y + f023.x * d23.x + f023.y * d23.y;
        float p1 = f101.x * d01.x + f101.y * d01.y + f123.x * d23.x + f123.y * d23.y;
        p0 += __shfl_xor_sync(0xffffffffu, p0, 1);
        p0 += __shfl_xor_sync(0xffffffffu, p0, 2);
        p1 += __shfl_xor_sync(0xffffffffu, p1, 1);
        p1 += __shfl_xor_sync(0xffffffffu, p1, 2);
        float e0 = __expf(p0 * 0.25f);   // scale = HIDDEN^-0.5
        float e1 = __expf(p1 * 0.25f);
        den += e0 + e1;
        a0 += e0 * f001.x + e1 * f101.x;
        a1 += e0 * f001.y + e1 * f101.y;
        a2 += e0 * f023.x + e1 * f123.x;
        a3 += e0 * f023.y + e1 * f123.y;
    }
    if (i < end) {
        int s0 = g_col[i];
        uint2 u0 = *reinterpret_cast<const uint2*>(fp + s0 * 128 + lane * 4);
        float2 f001 = __half22float2(*reinterpret_cast<__half2*>(&u0.x));
        float2 f023 = __half22float2(*reinterpret_cast<__half2*>(&u0.y));
        float p0 = f001.x * d01.x + f001.y * d01.y + f023.x * d23.x + f023.y * d23.y;
        p0 += __shfl_xor_sync(0xffffffffu, p0, 1);
        p0 += __shfl_xor_sync(0xffffffffu, p0, 2);
        float e0 = __expf(p0 * 0.25f);
        den += e0;
        a0 += e0 * f001.x; a1 += e0 * f001.y; a2 += e0 * f023.x; a3 += e0 * f023.y;
    }

    float inv = 1.f / fmaxf(den, 1e-9f);
    float4 o;
    o.x = eluf(a0 * inv);
    o.y = eluf(a1 * inv);
    o.z = eluf(a2 * inv);
    o.w = eluf(a3 * inv);
    *reinterpret_cast<float4*>(g_h1 + w * 128 + lane * 4) = o;
}

// ---------------- fused GAT layer 2 (fp16 gathers) ----------------
__global__ __launch_bounds__(256) void k_gat2(float* __restrict__ out) {
    int w = (blockIdx.x * blockDim.x + threadIdx.x) >> 5;
    if (w >= N_NODES) return;
    int lane = threadIdx.x & 31;

    const __half* fp = g_feat2h;
    float2 fd = __half22float2(*reinterpret_cast<const __half2*>(fp + w * 64 + lane * 2));
    float a0 = 0.f, a1 = 0.f, den = 0.f;

    int i = g_rs[w], end = g_rs[w + 1];
    for (; i + 1 < end; i += 2) {
        int s0 = g_col[i], s1 = g_col[i + 1];
        float2 f0 = __half22float2(*reinterpret_cast<const __half2*>(fp + s0 * 64 + lane * 2));
        float2 f1 = __half22float2(*reinterpret_cast<const __half2*>(fp + s1 * 64 + lane * 2));
        float p0 = f0.x * fd.x + f0.y * fd.y;
        float p1 = f1.x * fd.x + f1.y * fd.y;
#pragma unroll
        for (int off = 16; off; off >>= 1) {
            p0 += __shfl_xor_sync(0xffffffffu, p0, off);
            p1 += __shfl_xor_sync(0xffffffffu, p1, off);
        }
        float e0 = __expf(p0 * 0.125f);  // scale = 64^-0.5
        float e1 = __expf(p1 * 0.125f);
        den += e0 + e1;
        a0 += e0 * f0.x + e1 * f1.x;
        a1 += e0 * f0.y + e1 * f1.y;
    }
    if (i < end) {
        int s0 = g_col[i];
        float2 f0 = __half22float2(*reinterpret_cast<const __half2*>(fp + s0 * 64 + lane * 2));
        float p0 = f0.x * fd.x + f0.y * fd.y;
#pragma unroll
        for (int off = 16; off; off >>= 1)
            p0 += __shfl_xor_sync(0xffffffffu, p0, off);
        float e0 = __expf(p0 * 0.125f);
        den += e0;
        a0 += e0 * f0.x;
        a1 += e0 * f0.y;
    }

    float inv = 1.f / fmaxf(den, 1e-9f);
    *reinterpret_cast<float2*>(out + w * 64 + lane * 2) = make_float2(a0 * inv, a1 * inv);
}

// ---------------- launch ----------------
extern "C" void kernel_launch(void* const* d_in, const int* in_sizes, int n_in,
                              void* d_out, int out_size) {
    const float* h   = (const float*)d_in[0];
    const float* W1  = (const float*)d_in[1];
    const float* W2  = (const float*)d_in[2];
    const int*   src = (const int*)d_in[3];
    const int*   dst = (const int*)d_in[4];
    float*       out = (float*)d_out;

    __half *p_f1h = nullptr, *p_f2h = nullptr;
    float  *p_h1 = nullptr;
    cudaGetSymbolAddress((void**)&p_f1h, g_feat1h);
    cudaGetSymbolAddress((void**)&p_h1, g_h1);
    cudaGetSymbolAddress((void**)&p_f2h, g_feat2h);

    const int TB = 256;
    k_reset<<<(N_NODES + TB - 1) / TB, TB>>>();
    k_hist<<<(N_EDGES + TB - 1) / TB, TB>>>(dst);
    k_scan<<<1, 1024>>>();
    k_fill<<<(N_EDGES + TB - 1) / TB, TB>>>(src, dst);

    const int GB = (N_NODES + 127) / 128;  // 391
    k_gemm<128><<<GB, 256>>>(h, W1, p_f1h, nullptr);        // feat1h = fp16(h @ W1)
    k_gat1<<<(N_NODES * 32 + TB - 1) / TB, TB>>>();         // h1 = elu(gat(feat1))
    k_gemm<64><<<GB, 256>>>(p_h1, W2, p_f2h, nullptr);      // feat2h = fp16(h1 @ W2)
    k_gat2<<<(N_NODES * 32 + TB - 1) / TB, TB>>>(out);      // out = gat(feat2)
}

// round 3
// speedup vs baseline: 1.2022x; 1.2022x over previous
#include <cuda_runtime.h>
#include <cuda_fp16.h>
#include <math.h>

#define N_NODES 50000
#define N_EDGES 1600000
// IN_DIM = 128, HEADS*HIDDEN = 128, OUT_DIM = 64

typedef unsigned long long u64;

// ---------------- static device scratch ----------------
__device__ int    g_deg[N_NODES];
__device__ int    g_rs[N_NODES + 1];
__device__ int    g_cur[N_NODES];
__device__ int    g_col[N_EDGES];
__device__ __half g_feat1h[N_NODES * 128];
__device__ float  g_h1[N_NODES * 128];
__device__ __half g_feat2h[N_NODES * 64];

// ---------------- packed f32x2 helpers (sm_103a) ----------------
__device__ __forceinline__ u64 pack2(float x, float y) {
    u64 r; asm("mov.b64 %0, {%1, %2};" : "=l"(r) : "f"(x), "f"(y)); return r;
}
__device__ __forceinline__ void unpack2(u64 v, float& x, float& y) {
    asm("mov.b64 {%0, %1}, %2;" : "=f"(x), "=f"(y) : "l"(v));
}
__device__ __forceinline__ u64 ffma2(u64 a, u64 b, u64 c) {
    u64 d; asm("fma.rn.f32x2 %0, %1, %2, %3;" : "=l"(d) : "l"(a), "l"(b), "l"(c)); return d;
}

// ---------------- CSR build ----------------
__global__ void k_hist(const int* __restrict__ dst) {
    int i = blockIdx.x * blockDim.x + threadIdx.x;
    int base = i * 4;
    if (base + 3 < N_EDGES) {
        int4 d = *reinterpret_cast<const int4*>(dst + base);
        atomicAdd(&g_deg[d.x], 1);
        atomicAdd(&g_deg[d.y], 1);
        atomicAdd(&g_deg[d.z], 1);
        atomicAdd(&g_deg[d.w], 1);
    } else {
        for (int j = base; j < N_EDGES; j++) atomicAdd(&g_deg[dst[j]], 1);
    }
}

__global__ void k_scan() {
    __shared__ int sums[1024];
    const int PER = (N_NODES + 1023) / 1024;  // 49
    int t = threadIdx.x;
    int beg = t * PER;
    int end = min(beg + PER, N_NODES);
    int s = 0;
    for (int i = beg; i < end; i++) s += g_deg[i];
    sums[t] = s;
    __syncthreads();
    for (int off = 1; off < 1024; off <<= 1) {
        int v = (t >= off) ? sums[t - off] : 0;
        __syncthreads();
        sums[t] += v;
        __syncthreads();
    }
    int run = (t == 0) ? 0 : sums[t - 1];
    for (int i = beg; i < end; i++) {
        g_rs[i]  = run;
        g_cur[i] = run;
        run += g_deg[i];
    }
    if (t == 1023) g_rs[N_NODES] = run;
}

__global__ void k_fill(const int* __restrict__ src, const int* __restrict__ dst) {
    int i = blockIdx.x * blockDim.x + threadIdx.x;
    if (i < N_EDGES) {
        int d = dst[i];
        int pos = atomicAdd(&g_cur[d], 1);
        g_col[pos] = src[i];
    }
}

// ---------------- GEMM (fp32x2 packed): Yh(fp16) = X[N,128] @ W[128,MOUT] ----------------
template <int MOUT>
__global__ __launch_bounds__(256) void k_gemm(const float* __restrict__ X,
                                              const float* __restrict__ W,
                                              __half* __restrict__ Yh,
                                              float* __restrict__ Yf) {
    constexpr int CPT = MOUT / 16;          // 8 or 4 cols per thread
    constexpr int CP2 = CPT / 2;            // packed col pairs
    __shared__ float Xs[128][33];
    __shared__ float Ws[32][MOUT];

    const int tid = threadIdx.x;
    const int tx = tid & 15;
    const int ty = tid >> 4;
    const int row0 = blockIdx.x * 128;

    u64 acc[8][CP2];
#pragma unroll
    for (int i = 0; i < 8; i++)
#pragma unroll
        for (int j = 0; j < CP2; j++) acc[i][j] = pack2(0.f, 0.f);

#pragma unroll
    for (int kt = 0; kt < 4; kt++) {
#pragma unroll
        for (int it = 0; it < 4; it++) {
            int idx = tid + it * 256;
            int r = idx >> 3, kq = idx & 7;
            float4 v = make_float4(0.f, 0.f, 0.f, 0.f);
            int gr = row0 + r;
            if (gr < N_NODES)
                v = *reinterpret_cast<const float4*>(X + gr * 128 + kt * 32 + kq * 4);
            Xs[r][kq * 4 + 0] = v.x;
            Xs[r][kq * 4 + 1] = v.y;
            Xs[r][kq * 4 + 2] = v.z;
            Xs[r][kq * 4 + 3] = v.w;
        }
        for (int idx = tid; idx < 32 * MOUT / 4; idx += 256) {
            int k = idx / (MOUT / 4), c4 = idx % (MOUT / 4);
            *reinterpret_cast<float4*>(&Ws[k][c4 * 4]) =
                *reinterpret_cast<const float4*>(W + (kt * 32 + k) * MOUT + c4 * 4);
        }
        __syncthreads();

#pragma unroll
        for (int kk = 0; kk < 32; kk++) {
            // b: packed column pairs read directly as 64-bit values
            u64 b2[CP2];
#pragma unroll
            for (int j = 0; j < CP2; j += 2) {
                ulonglong2 bb = *reinterpret_cast<const ulonglong2*>(&Ws[kk][tx * CPT + j * 2]);
                b2[j] = bb.x;
                if (j + 1 < CP2) b2[j + 1] = bb.y;
            }
            float a[8];
#pragma unroll
            for (int i = 0; i < 8; i++) a[i] = Xs[ty * 8 + i][kk];
#pragma unroll
            for (int i = 0; i < 8; i++) {
                u64 aa = pack2(a[i], a[i]);
#pragma unroll
                for (int j = 0; j < CP2; j++) acc[i][j] = ffma2(aa, b2[j], acc[i][j]);
            }
        }
        __syncthreads();
    }

#pragma unroll
    for (int i = 0; i < 8; i++) {
        int gr = row0 + ty * 8 + i;
        if (gr >= N_NODES) continue;
#pragma unroll
        for (int j = 0; j < CP2; j++) {
            float x, y;
            unpack2(acc[i][j], x, y);
            *reinterpret_cast<__half2*>(Yh + gr * MOUT + tx * CPT + j * 2) =
                __float22half2_rn(make_float2(x, y));
            if (Yf) {
                *reinterpret_cast<float2*>(Yf + gr * MOUT + tx * CPT + j * 2) =
                    make_float2(x, y);
            }
        }
    }
}

// ---------------- fused GAT layer 1 (fp16 gathers, 4x unrolled) ----------------
__device__ __forceinline__ float eluf(float x) {
    return x > 0.f ? x : expm1f(x);
}

__device__ __forceinline__ float dot4h(const __half* fp, int s, int lane,
                                       float dx, float dy, float dz, float dw,
                                       float4& f) {
    uint2 u = *reinterpret_cast<const uint2*>(fp + s * 128 + lane * 4);
    float2 f01 = __half22float2(*reinterpret_cast<__half2*>(&u.x));
    float2 f23 = __half22float2(*reinterpret_cast<__half2*>(&u.y));
    f = make_float4(f01.x, f01.y, f23.x, f23.y);
    return f01.x * dx + f01.y * dy + f23.x * dz + f23.y * dw;
}

__global__ __launch_bounds__(256) void k_gat1() {
    int w = (blockIdx.x * blockDim.x + threadIdx.x) >> 5;
    if (w >= N_NODES) return;
    int lane = threadIdx.x & 31;

    const __half* fp = g_feat1h;
    uint2 ud = *reinterpret_cast<const uint2*>(fp + w * 128 + lane * 4);
    float2 d01 = __half22float2(*reinterpret_cast<__half2*>(&ud.x));
    float2 d23 = __half22float2(*reinterpret_cast<__half2*>(&ud.y));
    const float dx = d01.x, dy = d01.y, dz = d23.x, dw = d23.y;

    float a0 = 0.f, a1 = 0.f, a2 = 0.f, a3 = 0.f, den = 0.f;

    int i = g_rs[w], end = g_rs[w + 1];
    for (; i + 3 < end; i += 4) {
        int s0 = g_col[i], s1 = g_col[i + 1], s2 = g_col[i + 2], s3 = g_col[i + 3];
        float4 f0, f1, f2, f3;
        float p0 = dot4h(fp, s0, lane, dx, dy, dz, dw, f0);
        float p1 = dot4h(fp, s1, lane, dx, dy, dz, dw, f1);
        float p2 = dot4h(fp, s2, lane, dx, dy, dz, dw, f2);
        float p3 = dot4h(fp, s3, lane, dx, dy, dz, dw, f3);
        p0 += __shfl_xor_sync(0xffffffffu, p0, 1);
        p1 += __shfl_xor_sync(0xffffffffu, p1, 1);
        p2 += __shfl_xor_sync(0xffffffffu, p2, 1);
        p3 += __shfl_xor_sync(0xffffffffu, p3, 1);
        p0 += __shfl_xor_sync(0xffffffffu, p0, 2);
        p1 += __shfl_xor_sync(0xffffffffu, p1, 2);
        p2 += __shfl_xor_sync(0xffffffffu, p2, 2);
        p3 += __shfl_xor_sync(0xffffffffu, p3, 2);
        float e0 = __expf(p0 * 0.25f);
        float e1 = __expf(p1 * 0.25f);
        float e2 = __expf(p2 * 0.25f);
        float e3 = __expf(p3 * 0.25f);
        den += (e0 + e1) + (e2 + e3);
        a0 += e0 * f0.x + e1 * f1.x + e2 * f2.x + e3 * f3.x;
        a1 += e0 * f0.y + e1 * f1.y + e2 * f2.y + e3 * f3.y;
        a2 += e0 * f0.z + e1 * f1.z + e2 * f2.z + e3 * f3.z;
        a3 += e0 * f0.w + e1 * f1.w + e2 * f2.w + e3 * f3.w;
    }
    for (; i < end; i++) {
        int s0 = g_col[i];
        float4 f0;
        float p0 = dot4h(fp, s0, lane, dx, dy, dz, dw, f0);
        p0 += __shfl_xor_sync(0xffffffffu, p0, 1);
        p0 += __shfl_xor_sync(0xffffffffu, p0, 2);
        float e0 = __expf(p0 * 0.25f);
        den += e0;
        a0 += e0 * f0.x; a1 += e0 * f0.y; a2 += e0 * f0.z; a3 += e0 * f0.w;
    }

    float inv = 1.f / fmaxf(den, 1e-9f);
    float4 o;
    o.x = eluf(a0 * inv);
    o.y = eluf(a1 * inv);
    o.z = eluf(a2 * inv);
    o.w = eluf(a3 * inv);
    *reinterpret_cast<float4*>(g_h1 + w * 128 + lane * 4) = o;
}

// ---------------- fused GAT layer 2 (fp16 gathers, 4x unrolled) ----------------
__global__ __launch_bounds__(256) void k_gat2(float* __restrict__ out) {
    int w = (blockIdx.x * blockDim.x + threadIdx.x) >> 5;
    if (w >= N_NODES) return;
    int lane = threadIdx.x & 31;

    const __half* fp = g_feat2h;
    float2 fd = __half22float2(*reinterpret_cast<const __half2*>(fp + w * 64 + lane * 2));
    float a0 = 0.f, a1 = 0.f, den = 0.f;

    int i = g_rs[w], end = g_rs[w + 1];
    for (; i + 3 < end; i += 4) {
        int s0 = g_col[i], s1 = g_col[i + 1], s2 = g_col[i + 2], s3 = g_col[i + 3];
        float2 f0 = __half22float2(*reinterpret_cast<const __half2*>(fp + s0 * 64 + lane * 2));
        float2 f1 = __half22float2(*reinterpret_cast<const __half2*>(fp + s1 * 64 + lane * 2));
        float2 f2 = __half22float2(*reinterpret_cast<const __half2*>(fp + s2 * 64 + lane * 2));
        float2 f3 = __half22float2(*reinterpret_cast<const __half2*>(fp + s3 * 64 + lane * 2));
        float p0 = f0.x * fd.x + f0.y * fd.y;
        float p1 = f1.x * fd.x + f1.y * fd.y;
        float p2 = f2.x * fd.x + f2.y * fd.y;
        float p3 = f3.x * fd.x + f3.y * fd.y;
#pragma unroll
        for (int off = 16; off; off >>= 1) {
            p0 += __shfl_xor_sync(0xffffffffu, p0, off);
            p1 += __shfl_xor_sync(0xffffffffu, p1, off);
            p2 += __shfl_xor_sync(0xffffffffu, p2, off);
            p3 += __shfl_xor_sync(0xffffffffu, p3, off);
        }
        float e0 = __expf(p0 * 0.125f);
        float e1 = __expf(p1 * 0.125f);
        float e2 = __expf(p2 * 0.125f);
        float e3 = __expf(p3 * 0.125f);
        den += (e0 + e1) + (e2 + e3);
        a0 += e0 * f0.x + e1 * f1.x + e2 * f2.x + e3 * f3.x;
        a1 += e0 * f0.y + e1 * f1.y + e2 * f2.y + e3 * f3.y;
    }
    for (; i < end; i++) {
        int s0 = g_col[i];
        float2 f0 = __half22float2(*reinterpret_cast<const __half2*>(fp + s0 * 64 + lane * 2));
        float p0 = f0.x * fd.x + f0.y * fd.y;
#pragma unroll
        for (int off = 16; off; off >>= 1)
            p0 += __shfl_xor_sync(0xffffffffu, p0, off);
        float e0 = __expf(p0 * 0.125f);
        den += e0;
        a0 += e0 * f0.x;
        a1 += e0 * f0.y;
    }

    float inv = 1.f / fmaxf(den, 1e-9f);
    *reinterpret_cast<float2*>(out + w * 64 + lane * 2) = make_float2(a0 * inv, a1 * inv);
}

// ---------------- launch ----------------
extern "C" void kernel_launch(void* const* d_in, const int* in_sizes, int n_in,
                              void* d_out, int out_size) {
    const float* h   = (const float*)d_in[0];
    const float* W1  = (const float*)d_in[1];
    const float* W2  = (const float*)d_in[2];
    const int*   src = (const int*)d_in[3];
    const int*   dst = (const int*)d_in[4];
    float*       out = (float*)d_out;

    __half *p_f1h = nullptr, *p_f2h = nullptr;
    float  *p_h1 = nullptr;
    int    *p_deg = nullptr;
    cudaGetSymbolAddress((void**)&p_f1h, g_feat1h);
    cudaGetSymbolAddress((void**)&p_h1, g_h1);
    cudaGetSymbolAddress((void**)&p_f2h, g_feat2h);
    cudaGetSymbolAddress((void**)&p_deg, g_deg);

    const int TB = 256;
    cudaMemsetAsync(p_deg, 0, N_NODES * sizeof(int));
    k_hist<<<(N_EDGES / 4 + TB - 1) / TB, TB>>>(dst);
    k_scan<<<1, 1024>>>();
    k_fill<<<(N_EDGES + TB - 1) / TB, TB>>>(src, dst);

    const int GB = (N_NODES + 127) / 128;  // 391
    k_gemm<128><<<GB, 256>>>(h, W1, p_f1h, nullptr);
    k_gat1<<<(N_NODES * 32 + TB - 1) / TB, TB>>>();
    k_gemm<64><<<GB, 256>>>(p_h1, W2, p_f2h, nullptr);
    k_gat2<<<(N_NODES * 32 + TB - 1) / TB, TB>>>(out);
}

// round 4
// speedup vs baseline: 1.3475x; 1.1209x over previous
#include <cuda_runtime.h>
#include <math.h>

#define N_NODES 50000
#define N_EDGES 1600000
// IN_DIM = 128, HEADS*HIDDEN = 128, OUT_DIM = 64

// ---------------- static device scratch ----------------
__device__ int   g_deg[N_NODES];
__device__ int   g_rs[N_NODES + 1];
__device__ int   g_cur[N_NODES];
__device__ int   g_col[N_EDGES];
__device__ float g_feat1[N_NODES * 128];
__device__ float g_h1[N_NODES * 128];
__device__ float g_feat2[N_NODES * 64];

// ---------------- CSR build ----------------
__global__ void k_hist(const int* __restrict__ dst) {
    int i = blockIdx.x * blockDim.x + threadIdx.x;
    int base = i * 4;
    if (base + 3 < N_EDGES) {
        int4 d = *reinterpret_cast<const int4*>(dst + base);
        atomicAdd(&g_deg[d.x], 1);
        atomicAdd(&g_deg[d.y], 1);
        atomicAdd(&g_deg[d.z], 1);
        atomicAdd(&g_deg[d.w], 1);
    } else {
        for (int j = base; j < N_EDGES; j++) atomicAdd(&g_deg[dst[j]], 1);
    }
}

__global__ void k_scan() {
    __shared__ int sums[1024];
    const int PER = (N_NODES + 1023) / 1024;  // 49
    int t = threadIdx.x;
    int beg = t * PER;
    int end = min(beg + PER, N_NODES);
    int s = 0;
    for (int i = beg; i < end; i++) s += g_deg[i];
    sums[t] = s;
    __syncthreads();
    for (int off = 1; off < 1024; off <<= 1) {
        int v = (t >= off) ? sums[t - off] : 0;
        __syncthreads();
        sums[t] += v;
        __syncthreads();
    }
    int run = (t == 0) ? 0 : sums[t - 1];
    for (int i = beg; i < end; i++) {
        g_rs[i]  = run;
        g_cur[i] = run;
        run += g_deg[i];
    }
    if (t == 1023) g_rs[N_NODES] = run;
}

__global__ void k_fill(const int* __restrict__ src, const int* __restrict__ dst) {
    int i = blockIdx.x * blockDim.x + threadIdx.x;
    int base = i * 4;
    if (base + 3 < N_EDGES) {
        int4 d = *reinterpret_cast<const int4*>(dst + base);
        int4 s = *reinterpret_cast<const int4*>(src + base);
        g_col[atomicAdd(&g_cur[d.x], 1)] = s.x;
        g_col[atomicAdd(&g_cur[d.y], 1)] = s.y;
        g_col[atomicAdd(&g_cur[d.z], 1)] = s.z;
        g_col[atomicAdd(&g_cur[d.w], 1)] = s.w;
    } else {
        for (int j = base; j < N_EDGES; j++)
            g_col[atomicAdd(&g_cur[dst[j]], 1)] = src[j];
    }
}

// ---------------- tf32 tensor-core GEMM: Y[N,MOUT] = X[N,128] @ W[128,MOUT] ----------------
__device__ __forceinline__ unsigned cvt_tf32(float x) {
    unsigned r;
    asm("cvt.rna.tf32.f32 %0, %1;" : "=r"(r) : "f"(x));
    return r;
}

__device__ __forceinline__ void mma_tf32(float c[4], unsigned a0, unsigned a1,
                                         unsigned a2, unsigned a3,
                                         unsigned b0, unsigned b1) {
    asm("mma.sync.aligned.m16n8k8.row.col.f32.tf32.tf32.f32 "
        "{%0,%1,%2,%3}, {%4,%5,%6,%7}, {%8,%9}, {%0,%1,%2,%3};"
        : "+f"(c[0]), "+f"(c[1]), "+f"(c[2]), "+f"(c[3])
        : "r"(a0), "r"(a1), "r"(a2), "r"(a3), "r"(b0), "r"(b1));
}

template <int MOUT>
__global__ __launch_bounds__(256) void k_gemm_tc(const float* __restrict__ X,
                                                 const float* __restrict__ W,
                                                 float* __restrict__ Y) {
    constexpr int NT = MOUT / 8;      // n8 tiles per warp
    constexpr int WS = MOUT + 8;      // Ws row stride (≡8 mod 32: 8*tc+g conflict-free)
    __shared__ unsigned Xs[128 * 36]; // stride 36 (≡4 mod 32: 4*g+tc conflict-free)
    __shared__ unsigned Ws[32 * WS];

    const int tid = threadIdx.x;
    const int lane = tid & 31;
    const int wid = tid >> 5;         // 8 warps, 16 rows each
    const int g = lane >> 2;          // 0..7
    const int tc = lane & 3;          // 0..3
    const int row0 = blockIdx.x * 128;

    float acc[NT][4];
#pragma unroll
    for (int nt = 0; nt < NT; nt++)
#pragma unroll
        for (int j = 0; j < 4; j++) acc[nt][j] = 0.f;

#pragma unroll
    for (int kt = 0; kt < 4; kt++) {
        // Xs chunk: 128 rows x 32 k (tf32-converted)
#pragma unroll
        for (int it = 0; it < 4; it++) {
            int idx = tid + it * 256;
            int r = idx >> 3, kq = idx & 7;
            float4 v = make_float4(0.f, 0.f, 0.f, 0.f);
            int gr = row0 + r;
            if (gr < N_NODES)
                v = *reinterpret_cast<const float4*>(X + gr * 128 + kt * 32 + kq * 4);
            uint4 u = make_uint4(cvt_tf32(v.x), cvt_tf32(v.y), cvt_tf32(v.z), cvt_tf32(v.w));
            *reinterpret_cast<uint4*>(&Xs[r * 36 + kq * 4]) = u;
        }
        // Ws chunk: 32 k x MOUT cols
        for (int idx = tid; idx < 32 * MOUT / 4; idx += 256) {
            int k = idx / (MOUT / 4), c4 = idx % (MOUT / 4);
            float4 wv = *reinterpret_cast<const float4*>(W + (kt * 32 + k) * MOUT + c4 * 4);
            uint4 u = make_uint4(cvt_tf32(wv.x), cvt_tf32(wv.y), cvt_tf32(wv.z), cvt_tf32(wv.w));
            *reinterpret_cast<uint4*>(&Ws[k * WS + c4 * 4]) = u;
        }
        __syncthreads();

#pragma unroll
        for (int k8 = 0; k8 < 4; k8++) {
            unsigned a0 = Xs[(wid * 16 + g) * 36 + k8 * 8 + tc];
            unsigned a1 = Xs[(wid * 16 + g + 8) * 36 + k8 * 8 + tc];
            unsigned a2 = Xs[(wid * 16 + g) * 36 + k8 * 8 + tc + 4];
            unsigned a3 = Xs[(wid * 16 + g + 8) * 36 + k8 * 8 + tc + 4];
#pragma unroll
            for (int nt = 0; nt < NT; nt++) {
                unsigned b0 = Ws[(k8 * 8 + tc) * WS + nt * 8 + g];
                unsigned b1 = Ws[(k8 * 8 + tc + 4) * WS + nt * 8 + g];
                mma_tf32(acc[nt], a0, a1, a2, a3, b0, b1);
            }
        }
        __syncthreads();
    }

    // epilogue
    int r0 = row0 + wid * 16 + g;
    int r1 = r0 + 8;
#pragma unroll
    for (int nt = 0; nt < NT; nt++) {
        int c = nt * 8 + tc * 2;
        if (r0 < N_NODES)
            *reinterpret_cast<float2*>(Y + r0 * MOUT + c) = make_float2(acc[nt][0], acc[nt][1]);
        if (r1 < N_NODES)
            *reinterpret_cast<float2*>(Y + r1 * MOUT + c) = make_float2(acc[nt][2], acc[nt][3]);
    }
}

// ---------------- fused GAT layer 1 (fp32 gathers, 4x unrolled) ----------------
__device__ __forceinline__ float eluf(float x) {
    return x > 0.f ? x : expm1f(x);
}

__global__ __launch_bounds__(256) void k_gat1() {
    int w = (blockIdx.x * blockDim.x + threadIdx.x) >> 5;
    if (w >= N_NODES) return;
    int lane = threadIdx.x & 31;

    const float* fp = g_feat1;
    float4 fd = *reinterpret_cast<const float4*>(fp + w * 128 + lane * 4);

    float a0 = 0.f, a1 = 0.f, a2 = 0.f, a3 = 0.f, den = 0.f;

    int i = g_rs[w], end = g_rs[w + 1];
    for (; i + 3 < end; i += 4) {
        int s0 = g_col[i], s1 = g_col[i + 1], s2 = g_col[i + 2], s3 = g_col[i + 3];
        float4 f0 = *reinterpret_cast<const float4*>(fp + s0 * 128 + lane * 4);
        float4 f1 = *reinterpret_cast<const float4*>(fp + s1 * 128 + lane * 4);
        float4 f2 = *reinterpret_cast<const float4*>(fp + s2 * 128 + lane * 4);
        float4 f3 = *reinterpret_cast<const float4*>(fp + s3 * 128 + lane * 4);
        float p0 = f0.x * fd.x + f0.y * fd.y + f0.z * fd.z + f0.w * fd.w;
        float p1 = f1.x * fd.x + f1.y * fd.y + f1.z * fd.z + f1.w * fd.w;
        float p2 = f2.x * fd.x + f2.y * fd.y + f2.z * fd.z + f2.w * fd.w;
        float p3 = f3.x * fd.x + f3.y * fd.y + f3.z * fd.z + f3.w * fd.w;
        p0 += __shfl_xor_sync(0xffffffffu, p0, 1);
        p1 += __shfl_xor_sync(0xffffffffu, p1, 1);
        p2 += __shfl_xor_sync(0xffffffffu, p2, 1);
        p3 += __shfl_xor_sync(0xffffffffu, p3, 1);
        p0 += __shfl_xor_sync(0xffffffffu, p0, 2);
        p1 += __shfl_xor_sync(0xffffffffu, p1, 2);
        p2 += __shfl_xor_sync(0xffffffffu, p2, 2);
        p3 += __shfl_xor_sync(0xffffffffu, p3, 2);
        float e0 = __expf(p0 * 0.25f);
        float e1 = __expf(p1 * 0.25f);
        float e2 = __expf(p2 * 0.25f);
        float e3 = __expf(p3 * 0.25f);
        den += (e0 + e1) + (e2 + e3);
        a0 += e0 * f0.x + e1 * f1.x + e2 * f2.x + e3 * f3.x;
        a1 += e0 * f0.y + e1 * f1.y + e2 * f2.y + e3 * f3.y;
        a2 += e0 * f0.z + e1 * f1.z + e2 * f2.z + e3 * f3.z;
        a3 += e0 * f0.w + e1 * f1.w + e2 * f2.w + e3 * f3.w;
    }
    for (; i < end; i++) {
        int s0 = g_col[i];
        float4 f0 = *reinterpret_cast<const float4*>(fp + s0 * 128 + lane * 4);
        float p0 = f0.x * fd.x + f0.y * fd.y + f0.z * fd.z + f0.w * fd.w;
        p0 += __shfl_xor_sync(0xffffffffu, p0, 1);
        p0 += __shfl_xor_sync(0xffffffffu, p0, 2);
        float e0 = __expf(p0 * 0.25f);
        den += e0;
        a0 += e0 * f0.x; a1 += e0 * f0.y; a2 += e0 * f0.z; a3 += e0 * f0.w;
    }

    float inv = 1.f / fmaxf(den, 1e-9f);
    float4 o;
    o.x = eluf(a0 * inv);
    o.y = eluf(a1 * inv);
    o.z = eluf(a2 * inv);
    o.w = eluf(a3 * inv);
    *reinterpret_cast<float4*>(g_h1 + w * 128 + lane * 4) = o;
}

// ---------------- fused GAT layer 2 (fp32 gathers, 4x unrolled) ----------------
__global__ __launch_bounds__(256) void k_gat2(float* __restrict__ out) {
    int w = (blockIdx.x * blockDim.x + threadIdx.x) >> 5;
    if (w >= N_NODES) return;
    int lane = threadIdx.x & 31;

    const float* fp = g_feat2;
    float2 fd = *reinterpret_cast<const float2*>(fp + w * 64 + lane * 2);
    float a0 = 0.f, a1 = 0.f, den = 0.f;

    int i = g_rs[w], end = g_rs[w + 1];
    for (; i + 3 < end; i += 4) {
        int s0 = g_col[i], s1 = g_col[i + 1], s2 = g_col[i + 2], s3 = g_col[i + 3];
        float2 f0 = *reinterpret_cast<const float2*>(fp + s0 * 64 + lane * 2);
        float2 f1 = *reinterpret_cast<const float2*>(fp + s1 * 64 + lane * 2);
        float2 f2 = *reinterpret_cast<const float2*>(fp + s2 * 64 + lane * 2);
        float2 f3 = *reinterpret_cast<const float2*>(fp + s3 * 64 + lane * 2);
        float p0 = f0.x * fd.x + f0.y * fd.y;
        float p1 = f1.x * fd.x + f1.y * fd.y;
        float p2 = f2.x * fd.x + f2.y * fd.y;
        float p3 = f3.x * fd.x + f3.y * fd.y;
#pragma unroll
        for (int off = 16; off; off >>= 1) {
            p0 += __shfl_xor_sync(0xffffffffu, p0, off);
            p1 += __shfl_xor_sync(0xffffffffu, p1, off);
            p2 += __shfl_xor_sync(0xffffffffu, p2, off);
            p3 += __shfl_xor_sync(0xffffffffu, p3, off);
        }
        float e0 = __expf(p0 * 0.125f);
        float e1 = __expf(p1 * 0.125f);
        float e2 = __expf(p2 * 0.125f);
        float e3 = __expf(p3 * 0.125f);
        den += (e0 + e1) + (e2 + e3);
        a0 += e0 * f0.x + e1 * f1.x + e2 * f2.x + e3 * f3.x;
        a1 += e0 * f0.y + e1 * f1.y + e2 * f2.y + e3 * f3.y;
    }
    for (; i < end; i++) {
        int s0 = g_col[i];
        float2 f0 = *reinterpret_cast<const float2*>(fp + s0 * 64 + lane * 2);
        float p0 = f0.x * fd.x + f0.y * fd.y;
#pragma unroll
        for (int off = 16; off; off >>= 1)
            p0 += __shfl_xor_sync(0xffffffffu, p0, off);
        float e0 = __expf(p0 * 0.125f);
        den += e0;
        a0 += e0 * f0.x;
        a1 += e0 * f0.y;
    }

    float inv = 1.f / fmaxf(den, 1e-9f);
    *reinterpret_cast<float2*>(out + w * 64 + lane * 2) = make_float2(a0 * inv, a1 * inv);
}

// ---------------- launch ----------------
extern "C" void kernel_launch(void* const* d_in, const int* in_sizes, int n_in,
                              void* d_out, int out_size) {
    const float* h   = (const float*)d_in[0];
    const float* W1  = (const float*)d_in[1];
    const float* W2  = (const float*)d_in[2];
    const int*   src = (const int*)d_in[3];
    const int*   dst = (const int*)d_in[4];
    float*       out = (float*)d_out;

    float *p_f1 = nullptr, *p_h1 = nullptr, *p_f2 = nullptr;
    int   *p_deg = nullptr;
    cudaGetSymbolAddress((void**)&p_f1, g_feat1);
    cudaGetSymbolAddress((void**)&p_h1, g_h1);
    cudaGetSymbolAddress((void**)&p_f2, g_feat2);
    cudaGetSymbolAddress((void**)&p_deg, g_deg);

    const int TB = 256;
    cudaMemsetAsync(p_deg, 0, N_NODES * sizeof(int));
    k_hist<<<(N_EDGES / 4 + TB - 1) / TB, TB>>>(dst);
    k_scan<<<1, 1024>>>();
    k_fill<<<(N_EDGES / 4 + TB - 1) / TB, TB>>>(src, dst);

    const int GB = (N_NODES + 127) / 128;  // 391
    k_gemm_tc<128><<<GB, 256>>>(h, W1, p_f1);
    k_gat1<<<(N_NODES * 32 + TB - 1) / TB, TB>>>();
    k_gemm_tc<64><<<GB, 256>>>(p_h1, W2, p_f2);
    k_gat2<<<(N_NODES * 32 + TB - 1) / TB, TB>>>(out);
}

// round 10
// speedup vs baseline: 1.4429x; 1.0708x over previous
#include <cuda_runtime.h>
#include <math.h>

#define N_NODES 50000
#define N_EDGES 1600000
// IN_DIM = 128, HEADS*HIDDEN = 128, OUT_DIM = 64

// ---------------- static device scratch ----------------
__device__ int   g_deg[N_NODES];
__device__ int   g_rs[N_NODES + 1];
__device__ int   g_cur[N_NODES];
__device__ int   g_col[N_EDGES];
__device__ float g_feat1[N_NODES * 128];
__device__ float g_h1[N_NODES * 128];
__device__ float g_feat2[N_NODES * 64];

// ---------------- CSR build ----------------
__global__ void k_hist(const int* __restrict__ dst) {
    int i = blockIdx.x * blockDim.x + threadIdx.x;
    int base = i * 4;
    if (base + 3 < N_EDGES) {
        int4 d = *reinterpret_cast<const int4*>(dst + base);
        atomicAdd(&g_deg[d.x], 1);
        atomicAdd(&g_deg[d.y], 1);
        atomicAdd(&g_deg[d.z], 1);
        atomicAdd(&g_deg[d.w], 1);
    } else {
        for (int j = base; j < N_EDGES; j++) atomicAdd(&g_deg[dst[j]], 1);
    }
}

__global__ void k_scan() {
    __shared__ int sums[1024];
    const int PER = (N_NODES + 1023) / 1024;  // 49
    int t = threadIdx.x;
    int beg = t * PER;
    int end = min(beg + PER, N_NODES);
    int s = 0;
    for (int i = beg; i < end; i++) s += g_deg[i];
    sums[t] = s;
    __syncthreads();
    for (int off = 1; off < 1024; off <<= 1) {
        int v = (t >= off) ? sums[t - off] : 0;
        __syncthreads();
        sums[t] += v;
        __syncthreads();
    }
    int run = (t == 0) ? 0 : sums[t - 1];
    for (int i = beg; i < end; i++) {
        g_rs[i]  = run;
        g_cur[i] = run;
        run += g_deg[i];
    }
    if (t == 1023) g_rs[N_NODES] = run;
}

__global__ void k_fill(const int* __restrict__ src, const int* __restrict__ dst) {
    int i = blockIdx.x * blockDim.x + threadIdx.x;
    int base = i * 4;
    if (base + 3 < N_EDGES) {
        int4 d = *reinterpret_cast<const int4*>(dst + base);
        int4 s = *reinterpret_cast<const int4*>(src + base);
        g_col[atomicAdd(&g_cur[d.x], 1)] = s.x;
        g_col[atomicAdd(&g_cur[d.y], 1)] = s.y;
        g_col[atomicAdd(&g_cur[d.z], 1)] = s.z;
        g_col[atomicAdd(&g_cur[d.w], 1)] = s.w;
    } else {
        for (int j = base; j < N_EDGES; j++)
            g_col[atomicAdd(&g_cur[dst[j]], 1)] = src[j];
    }
}

// ---------------- tf32 tensor-core GEMM ----------------
__device__ __forceinline__ unsigned cvt_tf32(float x) {
    unsigned r;
    asm("cvt.rna.tf32.f32 %0, %1;" : "=r"(r) : "f"(x));
    return r;
}

__device__ __forceinline__ void mma_tf32(float c[4], unsigned a0, unsigned a1,
                                         unsigned a2, unsigned a3,
                                         unsigned b0, unsigned b1) {
    asm("mma.sync.aligned.m16n8k8.row.col.f32.tf32.tf32.f32 "
        "{%0,%1,%2,%3}, {%4,%5,%6,%7}, {%8,%9}, {%0,%1,%2,%3};"
        : "+f"(c[0]), "+f"(c[1]), "+f"(c[2]), "+f"(c[3])
        : "r"(a0), "r"(a1), "r"(a2), "r"(a3), "r"(b0), "r"(b1));
}

template <int MOUT>
__global__ __launch_bounds__(256) void k_gemm_tc(const float* __restrict__ X,
                                                 const float* __restrict__ W,
                                                 float* __restrict__ Y) {
    constexpr int NT = MOUT / 8;
    constexpr int WS = MOUT + 8;
    __shared__ unsigned Xs[128 * 36];
    __shared__ unsigned Ws[32 * WS];

    const int tid = threadIdx.x;
    const int lane = tid & 31;
    const int wid = tid >> 5;
    const int g = lane >> 2;
    const int tc = lane & 3;
    const int row0 = blockIdx.x * 128;

    float acc[NT][4];
#pragma unroll
    for (int nt = 0; nt < NT; nt++)
#pragma unroll
        for (int j = 0; j < 4; j++) acc[nt][j] = 0.f;

#pragma unroll
    for (int kt = 0; kt < 4; kt++) {
#pragma unroll
        for (int it = 0; it < 4; it++) {
            int idx = tid + it * 256;
            int r = idx >> 3, kq = idx & 7;
            float4 v = make_float4(0.f, 0.f, 0.f, 0.f);
            int gr = row0 + r;
            if (gr < N_NODES)
                v = *reinterpret_cast<const float4*>(X + gr * 128 + kt * 32 + kq * 4);
            uint4 u = make_uint4(cvt_tf32(v.x), cvt_tf32(v.y), cvt_tf32(v.z), cvt_tf32(v.w));
            *reinterpret_cast<uint4*>(&Xs[r * 36 + kq * 4]) = u;
        }
        for (int idx = tid; idx < 32 * MOUT / 4; idx += 256) {
            int k = idx / (MOUT / 4), c4 = idx % (MOUT / 4);
            float4 wv = *reinterpret_cast<const float4*>(W + (kt * 32 + k) * MOUT + c4 * 4);
            uint4 u = make_uint4(cvt_tf32(wv.x), cvt_tf32(wv.y), cvt_tf32(wv.z), cvt_tf32(wv.w));
            *reinterpret_cast<uint4*>(&Ws[k * WS + c4 * 4]) = u;
        }
        __syncthreads();

#pragma unroll
        for (int k8 = 0; k8 < 4; k8++) {
            unsigned a0 = Xs[(wid * 16 + g) * 36 + k8 * 8 + tc];
            unsigned a1 = Xs[(wid * 16 + g + 8) * 36 + k8 * 8 + tc];
            unsigned a2 = Xs[(wid * 16 + g) * 36 + k8 * 8 + tc + 4];
            unsigned a3 = Xs[(wid * 16 + g + 8) * 36 + k8 * 8 + tc + 4];
#pragma unroll
            for (int nt = 0; nt < NT; nt++) {
                unsigned b0 = Ws[(k8 * 8 + tc) * WS + nt * 8 + g];
                unsigned b1 = Ws[(k8 * 8 + tc + 4) * WS + nt * 8 + g];
                mma_tf32(acc[nt], a0, a1, a2, a3, b0, b1);
            }
        }
        __syncthreads();
    }

    int r0 = row0 + wid * 16 + g;
    int r1 = r0 + 8;
#pragma unroll
    for (int nt = 0; nt < NT; nt++) {
        int c = nt * 8 + tc * 2;
        if (r0 < N_NODES)
            *reinterpret_cast<float2*>(Y + r0 * MOUT + c) = make_float2(acc[nt][0], acc[nt][1]);
        if (r1 < N_NODES)
            *reinterpret_cast<float2*>(Y + r1 * MOUT + c) = make_float2(acc[nt][2], acc[nt][3]);
    }
}

// ---------------- fused GAT layer 1: half-warp per node, 8 dims/lane ----------------
__device__ __forceinline__ float eluf(float x) {
    return x > 0.f ? x : expm1f(x);
}
__device__ __forceinline__ float dot4(float4 a, float4 b) {
    return a.x * b.x + a.y * b.y + a.z * b.z + a.w * b.w;
}

__global__ __launch_bounds__(256) void k_gat1() {
    int t = blockIdx.x * blockDim.x + threadIdx.x;
    int w = t >> 4;                       // node per half-warp
    if (w >= N_NODES) return;
    int lane = threadIdx.x & 15;          // lane within half-warp
    unsigned mask = 0xFFFFu << (threadIdx.x & 16);

    const float* fp = g_feat1;
    const float* bd = fp + w * 128 + lane * 8;
    float4 d0 = *reinterpret_cast<const float4*>(bd);
    float4 d1 = *reinterpret_cast<const float4*>(bd + 4);

    float c0 = 0.f, c1 = 0.f, c2 = 0.f, c3 = 0.f;
    float c4 = 0.f, c5 = 0.f, c6 = 0.f, c7 = 0.f;
    float den = 0.f;

    int i = g_rs[w], end = g_rs[w + 1];
    for (; i + 1 < end; i += 2) {
        int s0 = g_col[i], s1 = g_col[i + 1];
        const float* b0 = fp + s0 * 128 + lane * 8;
        const float* b1 = fp + s1 * 128 + lane * 8;
        float4 f00 = *reinterpret_cast<const float4*>(b0);
        float4 f01 = *reinterpret_cast<const float4*>(b0 + 4);
        float4 f10 = *reinterpret_cast<const float4*>(b1);
        float4 f11 = *reinterpret_cast<const float4*>(b1 + 4);
        float p0 = dot4(f00, d0) + dot4(f01, d1);
        float p1 = dot4(f10, d0) + dot4(f11, d1);
        // head = 16 dims = 2 lanes -> single shfl completes per-head dot
        p0 += __shfl_xor_sync(mask, p0, 1);
        p1 += __shfl_xor_sync(mask, p1, 1);
        float e0 = __expf(p0 * 0.25f);    // HIDDEN^-0.5
        float e1 = __expf(p1 * 0.25f);
        den += e0 + e1;
        c0 += e0 * f00.x + e1 * f10.x;
        c1 += e0 * f00.y + e1 * f10.y;
        c2 += e0 * f00.z + e1 * f10.z;
        c3 += e0 * f00.w + e1 * f10.w;
        c4 += e0 * f01.x + e1 * f11.x;
        c5 += e0 * f01.y + e1 * f11.y;
        c6 += e0 * f01.z + e1 * f11.z;
        c7 += e0 * f01.w + e1 * f11.w;
    }
    if (i < end) {
        int s0 = g_col[i];
        const float* b0 = fp + s0 * 128 + lane * 8;
        float4 f00 = *reinterpret_cast<const float4*>(b0);
        float4 f01 = *reinterpret_cast<const float4*>(b0 + 4);
        float p0 = dot4(f00, d0) + dot4(f01, d1);
        p0 += __shfl_xor_sync(mask, p0, 1);
        float e0 = __expf(p0 * 0.25f);
        den += e0;
        c0 += e0 * f00.x; c1 += e0 * f00.y; c2 += e0 * f00.z; c3 += e0 * f00.w;
        c4 += e0 * f01.x; c5 += e0 * f01.y; c6 += e0 * f01.z; c7 += e0 * f01.w;
    }

    float inv = 1.f / fmaxf(den, 1e-9f);
    float* op = g_h1 + w * 128 + lane * 8;
    float4 o0 = make_float4(eluf(c0 * inv), eluf(c1 * inv), eluf(c2 * inv), eluf(c3 * inv));
    float4 o1 = make_float4(eluf(c4 * inv), eluf(c5 * inv), eluf(c6 * inv), eluf(c7 * inv));
    *reinterpret_cast<float4*>(op) = o0;
    *reinterpret_cast<float4*>(op + 4) = o1;
}

// ---------------- fused GAT layer 2: half-warp per node, 4 dims/lane ----------------
__global__ __launch_bounds__(256) void k_gat2(float* __restrict__ out) {
    int t = blockIdx.x * blockDim.x + threadIdx.x;
    int w = t >> 4;
    if (w >= N_NODES) return;
    int lane = threadIdx.x & 15;
    unsigned mask = 0xFFFFu << (threadIdx.x & 16);

    const float* fp = g_feat2;
    float4 fd = *reinterpret_cast<const float4*>(fp + w * 64 + lane * 4);
    float c0 = 0.f, c1 = 0.f, c2 = 0.f, c3 = 0.f, den = 0.f;

    int i = g_rs[w], end = g_rs[w + 1];
    for (; i + 3 < end; i += 4) {
        int s0 = g_col[i], s1 = g_col[i + 1], s2 = g_col[i + 2], s3 = g_col[i + 3];
        float4 f0 = *reinterpret_cast<const float4*>(fp + s0 * 64 + lane * 4);
        float4 f1 = *reinterpret_cast<const float4*>(fp + s1 * 64 + lane * 4);
        float4 f2 = *reinterpret_cast<const float4*>(fp + s2 * 64 + lane * 4);
        float4 f3 = *reinterpret_cast<const float4*>(fp + s3 * 64 + lane * 4);
        float p0 = dot4(f0, fd);
        float p1 = dot4(f1, fd);
        float p2 = dot4(f2, fd);
        float p3 = dot4(f3, fd);
#pragma unroll
        for (int off = 8; off; off >>= 1) {
            p0 += __shfl_xor_sync(mask, p0, off);
            p1 += __shfl_xor_sync(mask, p1, off);
            p2 += __shfl_xor_sync(mask, p2, off);
            p3 += __shfl_xor_sync(mask, p3, off);
        }
        float e0 = __expf(p0 * 0.125f);   // 64^-0.5
        float e1 = __expf(p1 * 0.125f);
        float e2 = __expf(p2 * 0.125f);
        float e3 = __expf(p3 * 0.125f);
        den += (e0 + e1) + (e2 + e3);
        c0 += e0 * f0.x + e1 * f1.x + e2 * f2.x + e3 * f3.x;
        c1 += e0 * f0.y + e1 * f1.y + e2 * f2.y + e3 * f3.y;
        c2 += e0 * f0.z + e1 * f1.z + e2 * f2.z + e3 * f3.z;
        c3 += e0 * f0.w + e1 * f1.w + e2 * f2.w + e3 * f3.w;
    }
    for (; i < end; i++) {
        int s0 = g_col[i];
        float4 f0 = *reinterpret_cast<const float4*>(fp + s0 * 64 + lane * 4);
        float p0 = dot4(f0, fd);
#pragma unroll
        for (int off = 8; off; off >>= 1)
            p0 += __shfl_xor_sync(mask, p0, off);
        float e0 = __expf(p0 * 0.125f);
        den += e0;
        c0 += e0 * f0.x; c1 += e0 * f0.y; c2 += e0 * f0.z; c3 += e0 * f0.w;
    }

    float inv = 1.f / fmaxf(den, 1e-9f);
    *reinterpret_cast<float4*>(out + w * 64 + lane * 4) =
        make_float4(c0 * inv, c1 * inv, c2 * inv, c3 * inv);
}

// ---------------- launch (CSR chain || gemm1 via side stream) ----------------
extern "C" void kernel_launch(void* const* d_in, const int* in_sizes, int n_in,
                              void* d_out, int out_size) {
    const float* h   = (const float*)d_in[0];
    const float* W1  = (const float*)d_in[1];
    const float* W2  = (const float*)d_in[2];
    const int*   src = (const int*)d_in[3];
    const int*   dst = (const int*)d_in[4];
    float*       out = (float*)d_out;

    float *p_f1 = nullptr, *p_h1 = nullptr, *p_f2 = nullptr;
    int   *p_deg = nullptr;
    cudaGetSymbolAddress((void**)&p_f1, g_feat1);
    cudaGetSymbolAddress((void**)&p_h1, g_h1);
    cudaGetSymbolAddress((void**)&p_f2, g_feat2);
    cudaGetSymbolAddress((void**)&p_deg, g_deg);

    // one-time side stream + events; created on the first (uncaptured,
    // correctness) call only — never during graph capture.
    static cudaStream_t s_side = nullptr;
    static cudaEvent_t ev_fork = nullptr, ev_join = nullptr;
    if (s_side == nullptr) {
        cudaStreamCreateWithFlags(&s_side, cudaStreamNonBlocking);
        cudaEventCreateWithFlags(&ev_fork, cudaEventDisableTiming);
        cudaEventCreateWithFlags(&ev_join, cudaEventDisableTiming);
    }

    const int TB = 256;
    const int GB = (N_NODES + 127) / 128;  // 391

    // fork: gemm1 on side stream (independent of CSR build)
    cudaEventRecord(ev_fork, 0);
    cudaStreamWaitEvent(s_side, ev_fork, 0);
    k_gemm_tc<128><<<GB, 256, 0, s_side>>>(h, W1, p_f1);
    cudaEventRecord(ev_join, s_side);

    // main stream: CSR build
    cudaMemsetAsync(p_deg, 0, N_NODES * sizeof(int));
    k_hist<<<(N_EDGES / 4 + TB - 1) / TB, TB>>>(dst);
    k_scan<<<1, 1024>>>();
    k_fill<<<(N_EDGES / 4 + TB - 1) / TB, TB>>>(src, dst);

    // join, then the dependent chain
    cudaStreamWaitEvent(0, ev_join, 0);
    k_gat1<<<(N_NODES * 16 + TB - 1) / TB, TB>>>();
    k_gemm_tc<64><<<GB, 256>>>(p_h1, W2, p_f2);
    k_gat2<<<(N_NODES * 16 + TB - 1) / TB, TB>>>(out);
}

// round 11
// speedup vs baseline: 1.8378x; 1.2737x over previous
#include <cuda_runtime.h>
#include <cuda_fp16.h>
#include <math.h>

#define N_NODES 50000
#define N_EDGES 1600000
// IN_DIM = 128, HEADS*HIDDEN = 128, OUT_DIM = 64

// ---------------- static device scratch ----------------
__device__ int    g_deg[N_NODES];
__device__ int    g_rs[N_NODES + 1];
__device__ int    g_rank[N_EDGES];
__device__ int    g_col[N_EDGES];
__device__ __half g_feat1h[N_NODES * 128];
__device__ float  g_h1[N_NODES * 128];
__device__ __half g_feat2h[N_NODES * 64];

// ---------------- CSR build (rank trick: atomics only in hist) ----------------
__global__ void k_hist(const int* __restrict__ dst) {
    int i = blockIdx.x * blockDim.x + threadIdx.x;
    int base = i * 4;
    if (base + 3 < N_EDGES) {
        int4 d = *reinterpret_cast<const int4*>(dst + base);
        int4 r;
        r.x = atomicAdd(&g_deg[d.x], 1);
        r.y = atomicAdd(&g_deg[d.y], 1);
        r.z = atomicAdd(&g_deg[d.z], 1);
        r.w = atomicAdd(&g_deg[d.w], 1);
        *reinterpret_cast<int4*>(g_rank + base) = r;
    } else {
        for (int j = base; j < N_EDGES; j++)
            g_rank[j] = atomicAdd(&g_deg[dst[j]], 1);
    }
}

__global__ void k_scan() {
    __shared__ int sums[1024];
    const int PER = (N_NODES + 1023) / 1024;  // 49
    int t = threadIdx.x;
    int beg = t * PER;
    int end = min(beg + PER, N_NODES);
    int s = 0;
    for (int i = beg; i < end; i++) s += g_deg[i];
    sums[t] = s;
    __syncthreads();
    for (int off = 1; off < 1024; off <<= 1) {
        int v = (t >= off) ? sums[t - off] : 0;
        __syncthreads();
        sums[t] += v;
        __syncthreads();
    }
    int run = (t == 0) ? 0 : sums[t - 1];
    for (int i = beg; i < end; i++) {
        g_rs[i] = run;
        run += g_deg[i];
    }
    if (t == 1023) g_rs[N_NODES] = run;
}

// atomic-free scatter fill
__global__ void k_fill(const int* __restrict__ src, const int* __restrict__ dst) {
    int i = blockIdx.x * blockDim.x + threadIdx.x;
    int base = i * 4;
    if (base + 3 < N_EDGES) {
        int4 d = *reinterpret_cast<const int4*>(dst + base);
        int4 r = *reinterpret_cast<const int4*>(g_rank + base);
        int4 s = *reinterpret_cast<const int4*>(src + base);
        g_col[g_rs[d.x] + r.x] = s.x;
        g_col[g_rs[d.y] + r.y] = s.y;
        g_col[g_rs[d.z] + r.z] = s.z;
        g_col[g_rs[d.w] + r.w] = s.w;
    } else {
        for (int j = base; j < N_EDGES; j++)
            g_col[g_rs[dst[j]] + g_rank[j]] = src[j];
    }
}

// ---------------- tf32 tensor-core GEMM -> fp16 table ----------------
__device__ __forceinline__ unsigned cvt_tf32(float x) {
    unsigned r;
    asm("cvt.rna.tf32.f32 %0, %1;" : "=r"(r) : "f"(x));
    return r;
}

__device__ __forceinline__ void mma_tf32(float c[4], unsigned a0, unsigned a1,
                                         unsigned a2, unsigned a3,
                                         unsigned b0, unsigned b1) {
    asm("mma.sync.aligned.m16n8k8.row.col.f32.tf32.tf32.f32 "
        "{%0,%1,%2,%3}, {%4,%5,%6,%7}, {%8,%9}, {%0,%1,%2,%3};"
        : "+f"(c[0]), "+f"(c[1]), "+f"(c[2]), "+f"(c[3])
        : "r"(a0), "r"(a1), "r"(a2), "r"(a3), "r"(b0), "r"(b1));
}

template <int MOUT>
__global__ __launch_bounds__(256) void k_gemm_tc(const float* __restrict__ X,
                                                 const float* __restrict__ W,
                                                 __half* __restrict__ Yh) {
    constexpr int NT = MOUT / 8;
    constexpr int WS = MOUT + 8;
    __shared__ unsigned Xs[128 * 36];
    __shared__ unsigned Ws[32 * WS];

    const int tid = threadIdx.x;
    const int lane = tid & 31;
    const int wid = tid >> 5;
    const int g = lane >> 2;
    const int tc = lane & 3;
    const int row0 = blockIdx.x * 128;

    float acc[NT][4];
#pragma unroll
    for (int nt = 0; nt < NT; nt++)
#pragma unroll
        for (int j = 0; j < 4; j++) acc[nt][j] = 0.f;

#pragma unroll
    for (int kt = 0; kt < 4; kt++) {
#pragma unroll
        for (int it = 0; it < 4; it++) {
            int idx = tid + it * 256;
            int r = idx >> 3, kq = idx & 7;
            float4 v = make_float4(0.f, 0.f, 0.f, 0.f);
            int gr = row0 + r;
            if (gr < N_NODES)
                v = *reinterpret_cast<const float4*>(X + gr * 128 + kt * 32 + kq * 4);
            uint4 u = make_uint4(cvt_tf32(v.x), cvt_tf32(v.y), cvt_tf32(v.z), cvt_tf32(v.w));
            *reinterpret_cast<uint4*>(&Xs[r * 36 + kq * 4]) = u;
        }
        for (int idx = tid; idx < 32 * MOUT / 4; idx += 256) {
            int k = idx / (MOUT / 4), c4 = idx % (MOUT / 4);
            float4 wv = *reinterpret_cast<const float4*>(W + (kt * 32 + k) * MOUT + c4 * 4);
            uint4 u = make_uint4(cvt_tf32(wv.x), cvt_tf32(wv.y), cvt_tf32(wv.z), cvt_tf32(wv.w));
            *reinterpret_cast<uint4*>(&Ws[k * WS + c4 * 4]) = u;
        }
        __syncthreads();

#pragma unroll
        for (int k8 = 0; k8 < 4; k8++) {
            unsigned a0 = Xs[(wid * 16 + g) * 36 + k8 * 8 + tc];
            unsigned a1 = Xs[(wid * 16 + g + 8) * 36 + k8 * 8 + tc];
            unsigned a2 = Xs[(wid * 16 + g) * 36 + k8 * 8 + tc + 4];
            unsigned a3 = Xs[(wid * 16 + g + 8) * 36 + k8 * 8 + tc + 4];
#pragma unroll
            for (int nt = 0; nt < NT; nt++) {
                unsigned b0 = Ws[(k8 * 8 + tc) * WS + nt * 8 + g];
                unsigned b1 = Ws[(k8 * 8 + tc + 4) * WS + nt * 8 + g];
                mma_tf32(acc[nt], a0, a1, a2, a3, b0, b1);
            }
        }
        __syncthreads();
    }

    int r0 = row0 + wid * 16 + g;
    int r1 = r0 + 8;
#pragma unroll
    for (int nt = 0; nt < NT; nt++) {
        int c = nt * 8 + tc * 2;
        if (r0 < N_NODES)
            *reinterpret_cast<__half2*>(Yh + r0 * MOUT + c) =
                __float22half2_rn(make_float2(acc[nt][0], acc[nt][1]));
        if (r1 < N_NODES)
            *reinterpret_cast<__half2*>(Yh + r1 * MOUT + c) =
                __float22half2_rn(make_float2(acc[nt][2], acc[nt][3]));
    }
}

// ---------------- fused GAT layer 1: half-warp/node, 8 fp16 dims/lane ----------------
__device__ __forceinline__ float eluf(float x) {
    return x > 0.f ? x : expm1f(x);
}

__device__ __forceinline__ void cvt8(uint4 u, float2& a, float2& b, float2& c, float2& d) {
    a = __half22float2(*reinterpret_cast<__half2*>(&u.x));
    b = __half22float2(*reinterpret_cast<__half2*>(&u.y));
    c = __half22float2(*reinterpret_cast<__half2*>(&u.z));
    d = __half22float2(*reinterpret_cast<__half2*>(&u.w));
}

__global__ __launch_bounds__(256) void k_gat1() {
    int t = blockIdx.x * blockDim.x + threadIdx.x;
    int w = t >> 4;
    if (w >= N_NODES) return;
    int lane = threadIdx.x & 15;
    unsigned mask = 0xFFFFu << (threadIdx.x & 16);

    const __half* fp = g_feat1h;
    uint4 ud = *reinterpret_cast<const uint4*>(fp + w * 128 + lane * 8);
    float2 d0, d1, d2, d3;
    cvt8(ud, d0, d1, d2, d3);

    float c0 = 0.f, c1 = 0.f, c2 = 0.f, c3 = 0.f;
    float c4 = 0.f, c5 = 0.f, c6 = 0.f, c7 = 0.f;
    float den = 0.f;

    int i = g_rs[w], end = g_rs[w + 1];
    for (; i + 1 < end; i += 2) {
        int s0 = g_col[i], s1 = g_col[i + 1];
        uint4 u0 = *reinterpret_cast<const uint4*>(fp + s0 * 128 + lane * 8);
        uint4 u1 = *reinterpret_cast<const uint4*>(fp + s1 * 128 + lane * 8);
        float2 a0, a1, a2, a3, b0, b1, b2, b3;
        cvt8(u0, a0, a1, a2, a3);
        cvt8(u1, b0, b1, b2, b3);
        float p0 = a0.x * d0.x + a0.y * d0.y + a1.x * d1.x + a1.y * d1.y
                 + a2.x * d2.x + a2.y * d2.y + a3.x * d3.x + a3.y * d3.y;
        float p1 = b0.x * d0.x + b0.y * d0.y + b1.x * d1.x + b1.y * d1.y
                 + b2.x * d2.x + b2.y * d2.y + b3.x * d3.x + b3.y * d3.y;
        p0 += __shfl_xor_sync(mask, p0, 1);
        p1 += __shfl_xor_sync(mask, p1, 1);
        float e0 = __expf(p0 * 0.25f);    // HIDDEN^-0.5
        float e1 = __expf(p1 * 0.25f);
        den += e0 + e1;
        c0 += e0 * a0.x + e1 * b0.x;
        c1 += e0 * a0.y + e1 * b0.y;
        c2 += e0 * a1.x + e1 * b1.x;
        c3 += e0 * a1.y + e1 * b1.y;
        c4 += e0 * a2.x + e1 * b2.x;
        c5 += e0 * a2.y + e1 * b2.y;
        c6 += e0 * a3.x + e1 * b3.x;
        c7 += e0 * a3.y + e1 * b3.y;
    }
    if (i < end) {
        int s0 = g_col[i];
        uint4 u0 = *reinterpret_cast<const uint4*>(fp + s0 * 128 + lane * 8);
        float2 a0, a1, a2, a3;
        cvt8(u0, a0, a1, a2, a3);
        float p0 = a0.x * d0.x + a0.y * d0.y + a1.x * d1.x + a1.y * d1.y
                 + a2.x * d2.x + a2.y * d2.y + a3.x * d3.x + a3.y * d3.y;
        p0 += __shfl_xor_sync(mask, p0, 1);
        float e0 = __expf(p0 * 0.25f);
        den += e0;
        c0 += e0 * a0.x; c1 += e0 * a0.y; c2 += e0 * a1.x; c3 += e0 * a1.y;
        c4 += e0 * a2.x; c5 += e0 * a2.y; c6 += e0 * a3.x; c7 += e0 * a3.y;
    }

    float inv = 1.f / fmaxf(den, 1e-9f);
    float* op = g_h1 + w * 128 + lane * 8;
    *reinterpret_cast<float4*>(op) =
        make_float4(eluf(c0 * inv), eluf(c1 * inv), eluf(c2 * inv), eluf(c3 * inv));
    *reinterpret_cast<float4*>(op + 4) =
        make_float4(eluf(c4 * inv), eluf(c5 * inv), eluf(c6 * inv), eluf(c7 * inv));
}

// ---------------- fused GAT layer 2: 8 lanes/node, 8 fp16 dims/lane ----------------
__global__ __launch_bounds__(256) void k_gat2(float* __restrict__ out) {
    int t = blockIdx.x * blockDim.x + threadIdx.x;
    int w = t >> 3;
    if (w >= N_NODES) return;
    int lane = threadIdx.x & 7;
    unsigned mask = 0xFFu << (threadIdx.x & 24);

    const __half* fp = g_feat2h;
    uint4 ud = *reinterpret_cast<const uint4*>(fp + w * 64 + lane * 8);
    float2 d0, d1, d2, d3;
    cvt8(ud, d0, d1, d2, d3);

    float c0 = 0.f, c1 = 0.f, c2 = 0.f, c3 = 0.f;
    float c4 = 0.f, c5 = 0.f, c6 = 0.f, c7 = 0.f;
    float den = 0.f;

    int i = g_rs[w], end = g_rs[w + 1];
    for (; i + 1 < end; i += 2) {
        int s0 = g_col[i], s1 = g_col[i + 1];
        uint4 u0 = *reinterpret_cast<const uint4*>(fp + s0 * 64 + lane * 8);
        uint4 u1 = *reinterpret_cast<const uint4*>(fp + s1 * 64 + lane * 8);
        float2 a0, a1, a2, a3, b0, b1, b2, b3;
        cvt8(u0, a0, a1, a2, a3);
        cvt8(u1, b0, b1, b2, b3);
        float p0 = a0.x * d0.x + a0.y * d0.y + a1.x * d1.x + a1.y * d1.y
                 + a2.x * d2.x + a2.y * d2.y + a3.x * d3.x + a3.y * d3.y;
        float p1 = b0.x * d0.x + b0.y * d0.y + b1.x * d1.x + b1.y * d1.y
                 + b2.x * d2.x + b2.y * d2.y + b3.x * d3.x + b3.y * d3.y;
#pragma unroll
        for (int off = 4; off; off >>= 1) {
            p0 += __shfl_xor_sync(mask, p0, off);
            p1 += __shfl_xor_sync(mask, p1, off);
        }
        float e0 = __expf(p0 * 0.125f);   // 64^-0.5
        float e1 = __expf(p1 * 0.125f);
        den += e0 + e1;
        c0 += e0 * a0.x + e1 * b0.x;
        c1 += e0 * a0.y + e1 * b0.y;
        c2 += e0 * a1.x + e1 * b1.x;
        c3 += e0 * a1.y + e1 * b1.y;
        c4 += e0 * a2.x + e1 * b2.x;
        c5 += e0 * a2.y + e1 * b2.y;
        c6 += e0 * a3.x + e1 * b3.x;
        c7 += e0 * a3.y + e1 * b3.y;
    }
    if (i < end) {
        int s0 = g_col[i];
        uint4 u0 = *reinterpret_cast<const uint4*>(fp + s0 * 64 + lane * 8);
        float2 a0, a1, a2, a3;
        cvt8(u0, a0, a1, a2, a3);
        float p0 = a0.x * d0.x + a0.y * d0.y + a1.x * d1.x + a1.y * d1.y
                 + a2.x * d2.x + a2.y * d2.y + a3.x * d3.x + a3.y * d3.y;
#pragma unroll
        for (int off = 4; off; off >>= 1)
            p0 += __shfl_xor_sync(mask, p0, off);
        float e0 = __expf(p0 * 0.125f);
        den += e0;
        c0 += e0 * a0.x; c1 += e0 * a0.y; c2 += e0 * a1.x; c3 += e0 * a1.y;
        c4 += e0 * a2.x; c5 += e0 * a2.y; c6 += e0 * a3.x; c7 += e0 * a3.y;
    }

    float inv = 1.f / fmaxf(den, 1e-9f);
    float* op = out + w * 64 + lane * 8;
    *reinterpret_cast<float4*>(op) = make_float4(c0 * inv, c1 * inv, c2 * inv, c3 * inv);
    *reinterpret_cast<float4*>(op + 4) = make_float4(c4 * inv, c5 * inv, c6 * inv, c7 * inv);
}

// ---------------- launch (CSR chain || gemm1 via side stream) ----------------
extern "C" void kernel_launch(void* const* d_in, const int* in_sizes, int n_in,
                              void* d_out, int out_size) {
    const float* h   = (const float*)d_in[0];
    const float* W1  = (const float*)d_in[1];
    const float* W2  = (const float*)d_in[2];
    const int*   src = (const int*)d_in[3];
    const int*   dst = (const int*)d_in[4];
    float*       out = (float*)d_out;

    __half *p_f1h = nullptr, *p_f2h = nullptr;
    float  *p_h1 = nullptr;
    int    *p_deg = nullptr;
    cudaGetSymbolAddress((void**)&p_f1h, g_feat1h);
    cudaGetSymbolAddress((void**)&p_h1, g_h1);
    cudaGetSymbolAddress((void**)&p_f2h, g_feat2h);
    cudaGetSymbolAddress((void**)&p_deg, g_deg);

    static cudaStream_t s_side = nullptr;
    static cudaEvent_t ev_fork = nullptr, ev_join = nullptr;
    if (s_side == nullptr) {
        cudaStreamCreateWithFlags(&s_side, cudaStreamNonBlocking);
        cudaEventCreateWithFlags(&ev_fork, cudaEventDisableTiming);
        cudaEventCreateWithFlags(&ev_join, cudaEventDisableTiming);
    }

    const int TB = 256;
    const int GB = (N_NODES + 127) / 128;  // 391
    const int EB = (N_EDGES / 4 + TB - 1) / TB;

    // fork: gemm1 on side stream (independent of CSR build)
    cudaEventRecord(ev_fork, 0);
    cudaStreamWaitEvent(s_side, ev_fork, 0);
    k_gemm_tc<128><<<GB, 256, 0, s_side>>>(h, W1, p_f1h);
    cudaEventRecord(ev_join, s_side);

    // main stream: CSR build
    cudaMemsetAsync(p_deg, 0, N_NODES * sizeof(int));
    k_hist<<<EB, TB>>>(dst);
    k_scan<<<1, 1024>>>();
    k_fill<<<EB, TB>>>(src, dst);

    // join, then the dependent chain
    cudaStreamWaitEvent(0, ev_join, 0);
    k_gat1<<<(N_NODES * 16 + TB - 1) / TB, TB>>>();
    k_gemm_tc<64><<<GB, 256>>>(p_h1, W2, p_f2h);
    k_gat2<<<(N_NODES * 8 + TB - 1) / TB, TB>>>(out);
}